// round 2
// baseline (speedup 1.0000x reference)
#include <cuda_runtime.h>

#define N 8192
#define BLOCK 256
#define ROWS_PER_CTA 8
#define CHUNKS 8          // per-thread float4 chunks: 8 * 4 * 256 = 8192 cols

// Per-column exponential factors (precomputed once, stage 1).
__device__ float g_p[N];  // exp(ndp_j / 20)
__device__ float g_q[N];  // exp(-ndp_j / 20)

// ---------------------------------------------------------------------------
// Stage 1: column-wise quantities. new_delta_pre + exp factors. 8192 elems.
// ---------------------------------------------------------------------------
__global__ void stdp_stage1(const float* __restrict__ spikes,
                            const float* __restrict__ dpre,
                            float* __restrict__ ndp_out) {
    int j = blockIdx.x * blockDim.x + threadIdx.x;
    if (j >= N) return;
    float ndp = (spikes[j] > 0.0f) ? 0.0f : (dpre[j] + 1.0f);
    ndp_out[j] = ndp;                 // new_delta_pre output region
    g_p[j] = expf(ndp * 0.05f);       // 1/20 = 0.05
    g_q[j] = expf(-ndp * 0.05f);
}

// ---------------------------------------------------------------------------
// Stage 2: fused GEVM + LIF + STDP weight update. One pass over W.
// Each CTA: stage spikes/ndp/p/q in smem (128KB), then for each of its rows:
//   - load W row into registers (32 KB), dot with spikes, block-reduce
//   - thread 0 computes LIF scalars + row exp factors
//   - all threads write updated W row from registers
// ---------------------------------------------------------------------------
__global__ void __launch_bounds__(BLOCK)
stdp_stage2(const float* __restrict__ W,
            const float* __restrict__ spikes,
            const float* __restrict__ membrane,
            const float* __restrict__ dfire,
            const float* __restrict__ ndp_g,   // = out + 2N (written by stage 1)
            float* __restrict__ out) {
    extern __shared__ float sm[];
    float* s_spk = sm;           // [N]
    float* s_ndp = sm + N;       // [N]
    float* s_p   = sm + 2 * N;   // [N]
    float* s_q   = sm + 3 * N;   // [N]
    __shared__ float s_red[BLOCK / 32];
    __shared__ float s_row[3];   // ndf, ep, en

    const int tid = threadIdx.x;

    // Cooperative fill of broadcast arrays (float4).
    {
        const float4* sp4 = (const float4*)spikes;
        const float4* nd4 = (const float4*)ndp_g;
        const float4* p4  = (const float4*)g_p;
        const float4* q4  = (const float4*)g_q;
        for (int i = tid; i < N / 4; i += BLOCK) {
            ((float4*)s_spk)[i] = sp4[i];
            ((float4*)s_ndp)[i] = nd4[i];
            ((float4*)s_p)[i]   = p4[i];
            ((float4*)s_q)[i]   = q4[i];
        }
    }
    __syncthreads();

    const int row0 = blockIdx.x * ROWS_PER_CTA;

    for (int r = 0; r < ROWS_PER_CTA; r++) {
        const int row = row0 + r;
        const float4* wrow = (const float4*)(W + (size_t)row * N);

        // Load row into registers + accumulate dot.
        float4 w[CHUNKS];
        float acc = 0.0f;
#pragma unroll
        for (int k = 0; k < CHUNKS; k++) {
            int c = tid + k * BLOCK;
            w[k] = wrow[c];
            float4 s = ((const float4*)s_spk)[c];
            acc += w[k].x * s.x + w[k].y * s.y + w[k].z * s.z + w[k].w * s.w;
        }

        // Block reduce.
#pragma unroll
        for (int o = 16; o > 0; o >>= 1)
            acc += __shfl_xor_sync(0xFFFFFFFFu, acc, o);
        if ((tid & 31) == 0) s_red[tid >> 5] = acc;
        __syncthreads();

        if (tid == 0) {
            float wsum = 0.0f;
#pragma unroll
            for (int i = 0; i < BLOCK / 32; i++) wsum += s_red[i];
            float mem   = membrane[row] * 0.99f + wsum;
            float spike = (mem > 1.0f) ? 1.0f : 0.0f;
            float nmem  = (spike > 0.0f) ? (mem - 0.8f) : mem;
            float ndf   = (spike > 0.0f) ? 0.0f : (dfire[row] + 1.0f);
            out[row]         = spike;   // out_spikes
            out[N + row]     = nmem;    // new_membrane
            out[3 * N + row] = ndf;     // new_delta_fire
            s_row[0] = ndf;
            s_row[1] = 0.005f * expf(-ndf * 0.05f);  // ep: potentiation row factor
            s_row[2] = 0.005f * expf(ndf * 0.05f);   // en: depression row factor
        }
        __syncthreads();

        const float ndf = s_row[0];
        const float ep  = s_row[1];
        const float en  = s_row[2];

        float4* orow = (float4*)(out + 4 * N + (size_t)row * N);
#pragma unroll
        for (int k = 0; k < CHUNKS; k++) {
            int c = tid + k * BLOCK;
            float4 nd = ((const float4*)s_ndp)[c];
            float4 p  = ((const float4*)s_p)[c];
            float4 q  = ((const float4*)s_q)[c];
            float4 o  = w[k];
            o.x += (ndf > nd.x) ? ep * p.x : ((ndf < nd.x) ? -en * q.x : 0.0f);
            o.y += (ndf > nd.y) ? ep * p.y : ((ndf < nd.y) ? -en * q.y : 0.0f);
            o.z += (ndf > nd.z) ? ep * p.z : ((ndf < nd.z) ? -en * q.z : 0.0f);
            o.w += (ndf > nd.w) ? ep * p.w : ((ndf < nd.w) ? -en * q.w : 0.0f);
            orow[c] = o;
        }
        // No extra sync needed: next iteration's s_red writes happen after the
        // barrier above; s_row reads of this iter complete before the next
        // post-reduce barrier.
    }
}

// ---------------------------------------------------------------------------
// kernel_launch: inputs in metadata order
//   0: in_spikes [8192]  1: weights [8192*8192]  2: membrane [8192]
//   3: delta_pre [8192]  4: delta_fire [8192]
// out layout: [out_spikes | new_membrane | new_delta_pre | new_delta_fire | new_weights]
// ---------------------------------------------------------------------------
extern "C" void kernel_launch(void* const* d_in, const int* in_sizes, int n_in,
                              void* d_out, int out_size) {
    const float* spikes   = (const float*)d_in[0];
    const float* weights  = (const float*)d_in[1];
    const float* membrane = (const float*)d_in[2];
    const float* dpre     = (const float*)d_in[3];
    const float* dfire    = (const float*)d_in[4];
    float* out = (float*)d_out;

    (void)in_sizes; (void)n_in; (void)out_size;

    const int smem_bytes = 4 * N * sizeof(float);  // 128 KB
    cudaFuncSetAttribute(stdp_stage2,
                         cudaFuncAttributeMaxDynamicSharedMemorySize, smem_bytes);

    stdp_stage1<<<N / BLOCK, BLOCK>>>(spikes, dpre, out + 2 * N);
    stdp_stage2<<<N / ROWS_PER_CTA, BLOCK, smem_bytes>>>(
        weights, spikes, membrane, dfire, out + 2 * N, out);
}

// round 3
// speedup vs baseline: 1.4597x; 1.4597x over previous
#include <cuda_runtime.h>

#define N 8192
#define BLOCK 256
#define ROWS_PER_CTA 8
#define CHUNKS 8          // per-thread float4 chunks: 8 * 4 * 256 = 8192 cols

// Per-column exponential factors (precomputed once, stage 1).
__device__ float g_p[N];  // exp(ndp_j / 20)   (== 1.0f exactly iff spike_j)
__device__ float g_q[N];  // exp(-ndp_j / 20)

// ---------------------------------------------------------------------------
// Stage 1: column-wise quantities. new_delta_pre + exp factors. 8192 elems.
// ---------------------------------------------------------------------------
__global__ void stdp_stage1(const float* __restrict__ spikes,
                            const float* __restrict__ dpre,
                            float* __restrict__ ndp_out) {
    int j = blockIdx.x * blockDim.x + threadIdx.x;
    if (j >= N) return;
    float ndp = (spikes[j] > 0.0f) ? 0.0f : (dpre[j] + 1.0f);
    ndp_out[j] = ndp;                 // new_delta_pre output region
    g_p[j] = expf(ndp * 0.05f);       // 1/20 = 0.05
    g_q[j] = expf(-ndp * 0.05f);
}

// ---------------------------------------------------------------------------
// Stage 2: fused GEVM + LIF + STDP weight update. One pass over W.
// smem: only p[N], q[N] (64 KB) -> 3 CTAs/SM.
//   spike_j      == (p_j == 1.0f)          (exp(0) == 1 exactly)
//   ndf >< ndp_j == E >< p_j               (expf strictly monotone on the
//                                           exact integer grid, same fn both sides)
// ---------------------------------------------------------------------------
__global__ void __launch_bounds__(BLOCK)
stdp_stage2(const float* __restrict__ W,
            const float* __restrict__ membrane,
            const float* __restrict__ dfire,
            float* __restrict__ out) {
    extern __shared__ float sm[];
    float* s_p = sm;           // [N]
    float* s_q = sm + N;       // [N]
    __shared__ float s_red[BLOCK / 32];
    __shared__ float s_row[3];   // E, ep, en

    const int tid = threadIdx.x;

    // Cooperative fill of broadcast arrays (float4).
    {
        const float4* p4 = (const float4*)g_p;
        const float4* q4 = (const float4*)g_q;
        for (int i = tid; i < N / 4; i += BLOCK) {
            ((float4*)s_p)[i] = p4[i];
            ((float4*)s_q)[i] = q4[i];
        }
    }
    __syncthreads();

    const int row0 = blockIdx.x * ROWS_PER_CTA;

    for (int r = 0; r < ROWS_PER_CTA; r++) {
        const int row = row0 + r;
        const float4* wrow = (const float4*)(W + (size_t)row * N);

        // Load row into registers (streaming) + accumulate dot.
        float4 w[CHUNKS];
        float acc = 0.0f;
#pragma unroll
        for (int k = 0; k < CHUNKS; k++) {
            int c = tid + k * BLOCK;
            w[k] = __ldcs(&wrow[c]);
            float4 p = ((const float4*)s_p)[c];
            acc += (p.x == 1.0f) ? w[k].x : 0.0f;
            acc += (p.y == 1.0f) ? w[k].y : 0.0f;
            acc += (p.z == 1.0f) ? w[k].z : 0.0f;
            acc += (p.w == 1.0f) ? w[k].w : 0.0f;
        }

        // Block reduce.
#pragma unroll
        for (int o = 16; o > 0; o >>= 1)
            acc += __shfl_xor_sync(0xFFFFFFFFu, acc, o);
        if ((tid & 31) == 0) s_red[tid >> 5] = acc;
        __syncthreads();

        if (tid == 0) {
            float wsum = 0.0f;
#pragma unroll
            for (int i = 0; i < BLOCK / 32; i++) wsum += s_red[i];
            float mem   = membrane[row] * 0.99f + wsum;
            float spike = (mem > 1.0f) ? 1.0f : 0.0f;
            float nmem  = (spike > 0.0f) ? (mem - 0.8f) : mem;
            float ndf   = (spike > 0.0f) ? 0.0f : (dfire[row] + 1.0f);
            out[row]         = spike;   // out_spikes
            out[N + row]     = nmem;    // new_membrane
            out[3 * N + row] = ndf;     // new_delta_fire
            s_row[0] = expf(ndf * 0.05f);            // E  (comparison key)
            s_row[1] = 0.005f * expf(-ndf * 0.05f);  // ep: potentiation row factor
            s_row[2] = 0.005f * expf(ndf * 0.05f);   // en: depression row factor
        }
        __syncthreads();

        const float E  = s_row[0];
        const float ep = s_row[1];
        const float en = s_row[2];

        float4* orow = (float4*)(out + 4 * N + (size_t)row * N);
#pragma unroll
        for (int k = 0; k < CHUNKS; k++) {
            int c = tid + k * BLOCK;
            float4 p = ((const float4*)s_p)[c];
            float4 q = ((const float4*)s_q)[c];
            float4 o = w[k];
            o.x += (E > p.x) ? ep * p.x : ((E < p.x) ? -en * q.x : 0.0f);
            o.y += (E > p.y) ? ep * p.y : ((E < p.y) ? -en * q.y : 0.0f);
            o.z += (E > p.z) ? ep * p.z : ((E < p.z) ? -en * q.z : 0.0f);
            o.w += (E > p.w) ? ep * p.w : ((E < p.w) ? -en * q.w : 0.0f);
            __stcs(&orow[c], o);
        }
    }
}

// ---------------------------------------------------------------------------
// kernel_launch: inputs in metadata order
//   0: in_spikes [8192]  1: weights [8192*8192]  2: membrane [8192]
//   3: delta_pre [8192]  4: delta_fire [8192]
// out layout: [out_spikes | new_membrane | new_delta_pre | new_delta_fire | new_weights]
// ---------------------------------------------------------------------------
extern "C" void kernel_launch(void* const* d_in, const int* in_sizes, int n_in,
                              void* d_out, int out_size) {
    const float* spikes   = (const float*)d_in[0];
    const float* weights  = (const float*)d_in[1];
    const float* membrane = (const float*)d_in[2];
    const float* dpre     = (const float*)d_in[3];
    const float* dfire    = (const float*)d_in[4];
    float* out = (float*)d_out;

    (void)in_sizes; (void)n_in; (void)out_size;

    const int smem_bytes = 2 * N * sizeof(float);  // 64 KB
    cudaFuncSetAttribute(stdp_stage2,
                         cudaFuncAttributeMaxDynamicSharedMemorySize, smem_bytes);

    stdp_stage1<<<N / BLOCK, BLOCK>>>(spikes, dpre, out + 2 * N);
    stdp_stage2<<<N / ROWS_PER_CTA, BLOCK, smem_bytes>>>(
        weights, membrane, dfire, out);
}

// round 4
// speedup vs baseline: 1.6475x; 1.1287x over previous
#include <cuda_runtime.h>

#define N 8192
#define BLOCK 256
#define CHUNKS 8          // per-thread float4 chunks: 8 * 4 * 256 = 8192 cols
#define GRID 296          // 148 SMs * 2 CTAs/SM, persistent

// Per-column exponential factors (precomputed once, stage 1).
__device__ float g_p[N];  // exp(ndp_j / 20)   (== 1.0f exactly iff spike_j)
__device__ float g_q[N];  // exp(-ndp_j / 20)

// ---------------------------------------------------------------------------
// Stage 1: column-wise quantities. new_delta_pre + exp factors. 8192 elems.
// ---------------------------------------------------------------------------
__global__ void stdp_stage1(const float* __restrict__ spikes,
                            const float* __restrict__ dpre,
                            float* __restrict__ ndp_out) {
    int j = blockIdx.x * blockDim.x + threadIdx.x;
    if (j >= N) return;
    float ndp = (spikes[j] > 0.0f) ? 0.0f : (dpre[j] + 1.0f);
    ndp_out[j] = ndp;                 // new_delta_pre output region
    g_p[j] = expf(ndp * 0.05f);       // 1/20 = 0.05
    g_q[j] = expf(-ndp * 0.05f);
}

// ---------------------------------------------------------------------------
// Row helpers for stage 2.
// ---------------------------------------------------------------------------
__device__ __forceinline__ void load_row(float4 (&w)[CHUNKS],
                                         const float* __restrict__ W,
                                         int row, int tid) {
    const float4* wrow = (const float4*)(W + (size_t)row * N);
#pragma unroll
    for (int k = 0; k < CHUNKS; k++)
        w[k] = __ldcs(&wrow[tid + k * BLOCK]);
}

__device__ __forceinline__ void process_row(
        float4 (&w)[CHUNKS], int row, int par,
        const float* __restrict__ s_p, const float* __restrict__ s_q,
        float (*s_red)[BLOCK / 32],
        const float* __restrict__ membrane,
        const float* __restrict__ dfire,
        float* __restrict__ out, int tid) {
    // Dot: spike_j == (p_j == 1.0f) exactly (exp(0) == 1).
    float acc = 0.0f;
#pragma unroll
    for (int k = 0; k < CHUNKS; k++) {
        int c = tid + k * BLOCK;
        float4 p = ((const float4*)s_p)[c];
        acc += (p.x == 1.0f) ? w[k].x : 0.0f;
        acc += (p.y == 1.0f) ? w[k].y : 0.0f;
        acc += (p.z == 1.0f) ? w[k].z : 0.0f;
        acc += (p.w == 1.0f) ? w[k].w : 0.0f;
    }
#pragma unroll
    for (int o = 16; o > 0; o >>= 1)
        acc += __shfl_xor_sync(0xFFFFFFFFu, acc, o);
    if ((tid & 31) == 0) s_red[par][tid >> 5] = acc;
    __syncthreads();   // the ONLY barrier per row (s_red parity-buffered)

    float wsum = 0.0f;
#pragma unroll
    for (int i = 0; i < BLOCK / 32; i++) wsum += s_red[par][i];

    // LIF + row scalars, computed redundantly by every thread (no serialization).
    float mem   = membrane[row] * 0.99f + wsum;
    float spike = (mem > 1.0f) ? 1.0f : 0.0f;
    float nmem  = (spike > 0.0f) ? (mem - 0.8f) : mem;
    float ndf   = (spike > 0.0f) ? 0.0f : (dfire[row] + 1.0f);
    if (tid == 0) {
        out[row]         = spike;   // out_spikes
        out[N + row]     = nmem;    // new_membrane
        out[3 * N + row] = ndf;     // new_delta_fire
    }
    float E  = expf(ndf * 0.05f);            // comparison key (monotone transfer)
    float ep = 0.005f * expf(-ndf * 0.05f);
    float en = 0.005f * E;

    float4* orow = (float4*)(out + 4 * N + (size_t)row * N);
#pragma unroll
    for (int k = 0; k < CHUNKS; k++) {
        int c = tid + k * BLOCK;
        float4 p = ((const float4*)s_p)[c];
        float4 q = ((const float4*)s_q)[c];
        float4 o = w[k];
        o.x += (E > p.x) ? ep * p.x : ((E < p.x) ? -en * q.x : 0.0f);
        o.y += (E > p.y) ? ep * p.y : ((E < p.y) ? -en * q.y : 0.0f);
        o.z += (E > p.z) ? ep * p.z : ((E < p.z) ? -en * q.z : 0.0f);
        o.w += (E > p.w) ? ep * p.w : ((E < p.w) ? -en * q.w : 0.0f);
        __stcs(&orow[c], o);
    }
}

// ---------------------------------------------------------------------------
// Stage 2: persistent CTAs, grid-stride over rows, double-buffered row
// registers so DRAM loads stay in flight through reduce/scalar/write phases.
// ---------------------------------------------------------------------------
__global__ void __launch_bounds__(BLOCK, 2)
stdp_stage2(const float* __restrict__ W,
            const float* __restrict__ membrane,
            const float* __restrict__ dfire,
            float* __restrict__ out) {
    extern __shared__ float sm[];
    float* s_p = sm;           // [N]
    float* s_q = sm + N;       // [N]
    __shared__ float s_red[2][BLOCK / 32];

    const int tid = threadIdx.x;

    // Cooperative fill of broadcast arrays (float4).
    {
        const float4* p4 = (const float4*)g_p;
        const float4* q4 = (const float4*)g_q;
        for (int i = tid; i < N / 4; i += BLOCK) {
            ((float4*)s_p)[i] = p4[i];
            ((float4*)s_q)[i] = q4[i];
        }
    }
    __syncthreads();

    float4 wA[CHUNKS], wB[CHUNKS];
    int row = blockIdx.x;
    int par = 0;
    bool useA = true;

    if (row < N) load_row(wA, W, row, tid);
    while (row < N) {
        int nrow = row + GRID;
        if (useA) {
            if (nrow < N) load_row(wB, W, nrow, tid);      // prefetch next row
            process_row(wA, row, par, s_p, s_q, s_red, membrane, dfire, out, tid);
        } else {
            if (nrow < N) load_row(wA, W, nrow, tid);
            process_row(wB, row, par, s_p, s_q, s_red, membrane, dfire, out, tid);
        }
        useA = !useA;
        par ^= 1;
        row = nrow;
    }
}

// ---------------------------------------------------------------------------
// kernel_launch: inputs in metadata order
//   0: in_spikes [8192]  1: weights [8192*8192]  2: membrane [8192]
//   3: delta_pre [8192]  4: delta_fire [8192]
// out layout: [out_spikes | new_membrane | new_delta_pre | new_delta_fire | new_weights]
// ---------------------------------------------------------------------------
extern "C" void kernel_launch(void* const* d_in, const int* in_sizes, int n_in,
                              void* d_out, int out_size) {
    const float* spikes   = (const float*)d_in[0];
    const float* weights  = (const float*)d_in[1];
    const float* membrane = (const float*)d_in[2];
    const float* dpre     = (const float*)d_in[3];
    const float* dfire    = (const float*)d_in[4];
    float* out = (float*)d_out;

    (void)in_sizes; (void)n_in; (void)out_size;

    const int smem_bytes = 2 * N * sizeof(float);  // 64 KB
    cudaFuncSetAttribute(stdp_stage2,
                         cudaFuncAttributeMaxDynamicSharedMemorySize, smem_bytes);

    stdp_stage1<<<N / BLOCK, BLOCK>>>(spikes, dpre, out + 2 * N);
    stdp_stage2<<<GRID, BLOCK, smem_bytes>>>(weights, membrane, dfire, out);
}

// round 5
// speedup vs baseline: 1.6580x; 1.0064x over previous
#include <cuda_runtime.h>

#define N 8192
#define BLOCK 256
#define CHUNKS 8          // per-thread float4 chunks: 8 * 4 * 256 = 8192 cols
#define GRID 296          // 148 SMs * 2 CTAs/SM, persistent

// ---------------------------------------------------------------------------
// Row helpers.
// ---------------------------------------------------------------------------
__device__ __forceinline__ void load_row(float4 (&w)[CHUNKS],
                                         const float* __restrict__ W,
                                         int row, int tid) {
    const float4* wrow = (const float4*)(W + (size_t)row * N);
#pragma unroll
    for (int k = 0; k < CHUNKS; k++)
        w[k] = __ldcs(&wrow[tid + k * BLOCK]);
}

__device__ __forceinline__ void process_row(
        float4 (&w)[CHUNKS], int row, int par,
        const float* __restrict__ s_p, const float* __restrict__ s_q,
        float (*s_red)[BLOCK / 32],
        const float* __restrict__ membrane,
        const float* __restrict__ dfire,
        float* __restrict__ out, int tid) {
    // Dot: spike_j == (p_j == 1.0f) exactly (exp(0) == 1).
    float acc = 0.0f;
#pragma unroll
    for (int k = 0; k < CHUNKS; k++) {
        int c = tid + k * BLOCK;
        float4 p = ((const float4*)s_p)[c];
        acc += (p.x == 1.0f) ? w[k].x : 0.0f;
        acc += (p.y == 1.0f) ? w[k].y : 0.0f;
        acc += (p.z == 1.0f) ? w[k].z : 0.0f;
        acc += (p.w == 1.0f) ? w[k].w : 0.0f;
    }
#pragma unroll
    for (int o = 16; o > 0; o >>= 1)
        acc += __shfl_xor_sync(0xFFFFFFFFu, acc, o);
    if ((tid & 31) == 0) s_red[par][tid >> 5] = acc;
    __syncthreads();   // the ONLY barrier per row (s_red parity-buffered)

    float wsum = 0.0f;
#pragma unroll
    for (int i = 0; i < BLOCK / 32; i++) wsum += s_red[par][i];

    // LIF + row scalars, computed redundantly by every thread (no serialization).
    float mem   = membrane[row] * 0.99f + wsum;
    float spike = (mem > 1.0f) ? 1.0f : 0.0f;
    float nmem  = (spike > 0.0f) ? (mem - 0.8f) : mem;
    float ndf   = (spike > 0.0f) ? 0.0f : (dfire[row] + 1.0f);
    if (tid == 0) {
        out[row]         = spike;   // out_spikes
        out[N + row]     = nmem;    // new_membrane
        out[3 * N + row] = ndf;     // new_delta_fire
    }
    float E  = expf(ndf * 0.05f);            // comparison key (monotone transfer)
    float ep = 0.005f * expf(-ndf * 0.05f);
    float en = 0.005f * E;

    float4* orow = (float4*)(out + 4 * N + (size_t)row * N);
#pragma unroll
    for (int k = 0; k < CHUNKS; k++) {
        int c = tid + k * BLOCK;
        float4 p = ((const float4*)s_p)[c];
        float4 q = ((const float4*)s_q)[c];
        float4 o = w[k];
        o.x += (E > p.x) ? ep * p.x : ((E < p.x) ? -en * q.x : 0.0f);
        o.y += (E > p.y) ? ep * p.y : ((E < p.y) ? -en * q.y : 0.0f);
        o.z += (E > p.z) ? ep * p.z : ((E < p.z) ? -en * q.z : 0.0f);
        o.w += (E > p.w) ? ep * p.w : ((E < p.w) ? -en * q.w : 0.0f);
        __stcs(&orow[c], o);
    }
}

// ---------------------------------------------------------------------------
// Fully fused single kernel: each CTA computes the column factors p/q into its
// own smem (deterministic recompute), CTA 0 writes new_delta_pre; then the
// persistent grid-stride row loop with double-buffered register rows.
// First row prefetch is issued BEFORE the expf prologue so DRAM is busy
// from cycle 0.
// ---------------------------------------------------------------------------
__global__ void __launch_bounds__(BLOCK, 2)
stdp_fused(const float* __restrict__ W,
           const float* __restrict__ spikes,
           const float* __restrict__ dpre,
           const float* __restrict__ membrane,
           const float* __restrict__ dfire,
           float* __restrict__ out) {
    extern __shared__ float sm[];
    float* s_p = sm;           // [N]  exp(ndp_j/20)   (== 1.0f exactly iff spike_j)
    float* s_q = sm + N;       // [N]  exp(-ndp_j/20)
    __shared__ float s_red[2][BLOCK / 32];

    const int tid = threadIdx.x;

    // Issue the first W-row loads immediately (long-scoreboard; overlaps expf).
    float4 wA[CHUNKS], wB[CHUNKS];
    int row = blockIdx.x;
    load_row(wA, W, row, tid);

    // Prologue: compute column factors into smem (replaces old stage-1 kernel).
    {
        const float4* sp4 = (const float4*)spikes;
        const float4* dp4 = (const float4*)dpre;
        float4* ndp_out4 = (float4*)(out + 2 * N);  // new_delta_pre region
        for (int i = tid; i < N / 4; i += BLOCK) {
            float4 s = sp4[i];
            float4 d = dp4[i];
            float4 nd;
            nd.x = (s.x > 0.0f) ? 0.0f : (d.x + 1.0f);
            nd.y = (s.y > 0.0f) ? 0.0f : (d.y + 1.0f);
            nd.z = (s.z > 0.0f) ? 0.0f : (d.z + 1.0f);
            nd.w = (s.w > 0.0f) ? 0.0f : (d.w + 1.0f);
            if (blockIdx.x == 0) ndp_out4[i] = nd;
            float4 p, q;
            p.x = expf(nd.x * 0.05f);  q.x = expf(-nd.x * 0.05f);
            p.y = expf(nd.y * 0.05f);  q.y = expf(-nd.y * 0.05f);
            p.z = expf(nd.z * 0.05f);  q.z = expf(-nd.z * 0.05f);
            p.w = expf(nd.w * 0.05f);  q.w = expf(-nd.w * 0.05f);
            ((float4*)s_p)[i] = p;
            ((float4*)s_q)[i] = q;
        }
    }
    __syncthreads();

    int par = 0;
    bool useA = true;
    while (row < N) {
        int nrow = row + GRID;
        if (useA) {
            if (nrow < N) load_row(wB, W, nrow, tid);      // prefetch next row
            process_row(wA, row, par, s_p, s_q, s_red, membrane, dfire, out, tid);
        } else {
            if (nrow < N) load_row(wA, W, nrow, tid);
            process_row(wB, row, par, s_p, s_q, s_red, membrane, dfire, out, tid);
        }
        useA = !useA;
        par ^= 1;
        row = nrow;
    }
}

// ---------------------------------------------------------------------------
// kernel_launch: inputs in metadata order
//   0: in_spikes [8192]  1: weights [8192*8192]  2: membrane [8192]
//   3: delta_pre [8192]  4: delta_fire [8192]
// out layout: [out_spikes | new_membrane | new_delta_pre | new_delta_fire | new_weights]
// ---------------------------------------------------------------------------
extern "C" void kernel_launch(void* const* d_in, const int* in_sizes, int n_in,
                              void* d_out, int out_size) {
    const float* spikes   = (const float*)d_in[0];
    const float* weights  = (const float*)d_in[1];
    const float* membrane = (const float*)d_in[2];
    const float* dpre     = (const float*)d_in[3];
    const float* dfire    = (const float*)d_in[4];
    float* out = (float*)d_out;

    (void)in_sizes; (void)n_in; (void)out_size;

    const int smem_bytes = 2 * N * sizeof(float);  // 64 KB
    cudaFuncSetAttribute(stdp_fused,
                         cudaFuncAttributeMaxDynamicSharedMemorySize, smem_bytes);

    stdp_fused<<<GRID, BLOCK, smem_bytes>>>(weights, spikes, dpre,
                                            membrane, dfire, out);
}